// round 1
// baseline (speedup 1.0000x reference)
#include <cuda_runtime.h>
#include <math.h>

#define BATCH   4096
#define LATENT  2048
#define ZDIM    128
#define NROWS   8192        // 2*BATCH
#define KC      32          // ZDIM/4 float4 chunks
#define TDIM    128         // tile size
#define NTILES  64          // NROWS / TDIM
#define TEMP_INV 2.0f
#define PRIOR        0.3f
#define PRIOR_PRIME  0.5f

// ---------------- scratch (device globals: no allocations allowed) ----------
__device__ float g_zn[NROWS * ZDIM];   // normalized z, fp32
__device__ float g_S[NROWS];           // per-row sum of exp(sim), diag excluded
__device__ float g_acc[8];             // 0..2: ypos/yposinv/yunl for h_i
                                       // 3..5: same for h_j
                                       // 6: sum of pos logits (already /TEMP)

// ---------------- init: zero accumulators every invocation ------------------
__global__ void init_kernel() {
    int i = blockIdx.x * blockDim.x + threadIdx.x;
    if (i < NROWS) g_S[i] = 0.0f;
    if (i < 8) g_acc[i] = 0.0f;
}

// ---------------- PU branch: logits + sigmoid sums --------------------------
// one warp per row; rows 0..4095 -> h_i, 4096..8191 -> h_j
__global__ void pu_kernel(const float* __restrict__ h_i,
                          const float* __restrict__ h_j,
                          const float* __restrict__ W,
                          const float* __restrict__ b,
                          const int*   __restrict__ target) {
    int gw   = (blockIdx.x * blockDim.x + threadIdx.x) >> 5;
    int lane = threadIdx.x & 31;
    if (gw >= 2 * BATCH) return;
    bool is_i = (gw < BATCH);
    int row = is_i ? gw : gw - BATCH;
    const float4* hv = (const float4*)((is_i ? h_i : h_j) + (size_t)row * LATENT);
    const float4* wv = (const float4*)W;

    float acc = 0.0f;
#pragma unroll
    for (int it = 0; it < LATENT / 128; ++it) {
        float4 a = hv[lane + it * 32];
        float4 w = wv[lane + it * 32];
        acc += a.x * w.x + a.y * w.y + a.z * w.z + a.w * w.w;
    }
#pragma unroll
    for (int m = 16; m; m >>= 1) acc += __shfl_xor_sync(0xffffffffu, acc, m);

    if (lane == 0) {
        float logit = acc + b[0];
        int t = target[row];
        int base = is_i ? 0 : 3;
        float sig_neg = 1.0f / (1.0f + __expf(logit));   // sigmoid(-logit)
        float sig_pos = 1.0f / (1.0f + __expf(-logit));  // sigmoid(+logit)
        if (t == 1) {
            atomicAdd(&g_acc[base + 0], sig_neg);  // y_pos
            atomicAdd(&g_acc[base + 1], sig_pos);  // y_pos_inv
        } else {
            atomicAdd(&g_acc[base + 2], sig_pos);  // y_unl
        }
    }
}

// ---------------- normalize z rows ------------------------------------------
// one warp per row (128 floats = 4 per lane)
__global__ void norm_kernel(const float* __restrict__ z_i,
                            const float* __restrict__ z_j) {
    int gw   = (blockIdx.x * blockDim.x + threadIdx.x) >> 5;
    int lane = threadIdx.x & 31;
    if (gw >= NROWS) return;
    const float* z = (gw < BATCH) ? (z_i + (size_t)gw * ZDIM)
                                  : (z_j + (size_t)(gw - BATCH) * ZDIM);
    float4 v = ((const float4*)z)[lane];
    float ss = v.x * v.x + v.y * v.y + v.z * v.z + v.w * v.w;
#pragma unroll
    for (int m = 16; m; m >>= 1) ss += __shfl_xor_sync(0xffffffffu, ss, m);
    float scale = 1.0f / fmaxf(sqrtf(ss), 1e-8f);
    v.x *= scale; v.y *= scale; v.z *= scale; v.w *= scale;
    ((float4*)(g_zn + (size_t)gw * ZDIM))[lane] = v;
}

// ---------------- sum of positive-pair logits -------------------------------
// one warp per row; (i + BATCH) % NROWS == i ^ BATCH
__global__ void pos_kernel() {
    __shared__ float pr[8];
    int gw   = blockIdx.x * 8 + (threadIdx.x >> 5);
    int lane = threadIdx.x & 31;
    float d = 0.0f;
    if (gw < NROWS) {
        float4 a = ((const float4*)g_zn)[gw * KC + lane];
        float4 c = ((const float4*)g_zn)[(gw ^ BATCH) * KC + lane];
        d = a.x * c.x + a.y * c.y + a.z * c.z + a.w * c.w;
    }
#pragma unroll
    for (int m = 16; m; m >>= 1) d += __shfl_xor_sync(0xffffffffu, d, m);
    if (lane == 0) pr[threadIdx.x >> 5] = d;
    __syncthreads();
    if (threadIdx.x == 0) {
        float s = 0.0f;
#pragma unroll
        for (int k = 0; k < 8; ++k) s += pr[k];
        atomicAdd(&g_acc[6], s * TEMP_INV);
    }
}

// ---------------- main similarity kernel ------------------------------------
// Symmetric tiling: 64x64 tile grid, only bj >= bi blocks do work.
// Each block: 128x128 tile of sim, K=128 fully in SMEM (XOR swizzle),
// 8x8 micro-tile per thread, exp + row/col partial sums -> atomicAdd g_S.
__global__ __launch_bounds__(256, 1)
void sim_kernel() {
    int bi = blockIdx.y, bj = blockIdx.x;
    if (bj < bi) return;

    extern __shared__ float smem[];
    float* As = smem;                       // 128 rows x 32 float4 (swizzled)
    float* Bs = smem + TDIM * ZDIM;         // same
    float* ColRed = smem + 2 * TDIM * ZDIM; // 8 warps x 128 cols

    int tid  = threadIdx.x;
    int tx   = tid & 15, ty = tid >> 4;
    int lane = tid & 31, wrp = tid >> 5;
    int rowbase = bi * TDIM, colbase = bj * TDIM;

    // cooperative load, XOR-swizzled on float4 chunk index
    const float4* Z = (const float4*)g_zn;
#pragma unroll
    for (int l = 0; l < 16; ++l) {
        int idx = tid + l * 256;          // 0..4095
        int r  = idx >> 5;
        int kc = idx & 31;
        int kcs = kc ^ ((r >> 3) & 7);
        ((float4*)As)[r * KC + kcs] = Z[(rowbase + r) * KC + kc];
        ((float4*)Bs)[r * KC + kcs] = Z[(colbase + r) * KC + kc];
    }
    __syncthreads();

    float acc[8][8];
#pragma unroll
    for (int i = 0; i < 8; ++i)
#pragma unroll
        for (int j = 0; j < 8; ++j) acc[i][j] = 0.0f;

    int ra = ty * 8, ca = tx * 8;
    int sa = ty & 7, sb = tx & 7;   // swizzle keys for this thread's rows/cols
#pragma unroll 4
    for (int kc = 0; kc < KC; ++kc) {
        float4 a4[8], b4[8];
#pragma unroll
        for (int i = 0; i < 8; ++i) {
            a4[i] = ((const float4*)As)[(ra + i) * KC + (kc ^ sa)];
            b4[i] = ((const float4*)Bs)[(ca + i) * KC + (kc ^ sb)];
        }
#pragma unroll
        for (int i = 0; i < 8; ++i)
#pragma unroll
            for (int j = 0; j < 8; ++j) {
                acc[i][j] += a4[i].x * b4[j].x;
                acc[i][j] += a4[i].y * b4[j].y;
                acc[i][j] += a4[i].z * b4[j].z;
                acc[i][j] += a4[i].w * b4[j].w;
            }
    }

    // exp + partial sums (sims bounded by 2 in magnitude -> no max needed)
    bool diag = (bi == bj);
    float rowsum[8], colsum[8];
#pragma unroll
    for (int i = 0; i < 8; ++i) { rowsum[i] = 0.0f; colsum[i] = 0.0f; }
#pragma unroll
    for (int i = 0; i < 8; ++i) {
        int gr = rowbase + ra + i;
#pragma unroll
        for (int j = 0; j < 8; ++j) {
            int gc = colbase + ca + j;
            float e = __expf(acc[i][j] * TEMP_INV);
            if (gr != gc) { rowsum[i] += e; colsum[j] += e; }
        }
    }

    // row reduction over tx (lanes within each 16-lane half)
#pragma unroll
    for (int m = 1; m < 16; m <<= 1)
#pragma unroll
        for (int i = 0; i < 8; ++i)
            rowsum[i] += __shfl_xor_sync(0xffffffffu, rowsum[i], m);
    if ((lane & 15) == 0) {
#pragma unroll
        for (int i = 0; i < 8; ++i)
            atomicAdd(&g_S[rowbase + ra + i], rowsum[i]);
    }

    // column reduction (symmetric contribution) — off-diagonal blocks only
    if (!diag) {
#pragma unroll
        for (int i = 0; i < 8; ++i)
            colsum[i] += __shfl_xor_sync(0xffffffffu, colsum[i], 16);
        if (lane < 16) {
#pragma unroll
            for (int i = 0; i < 8; ++i)
                ColRed[wrp * TDIM + ca + i] = colsum[i];
        }
        __syncthreads();
        if (tid < TDIM) {
            float s = 0.0f;
#pragma unroll
            for (int w = 0; w < 8; ++w) s += ColRed[w * TDIM + tid];
            atomicAdd(&g_S[colbase + tid], s);
        }
    }
}

// ---------------- finalize ---------------------------------------------------
__global__ void final_kernel(const int* __restrict__ target,
                             const float* __restrict__ w_onnpu,
                             float* __restrict__ out) {
    __shared__ float redf[256];
    __shared__ int   redi[256];
    int tid = threadIdx.x;
    float lsum = 0.0f;
    for (int i = tid; i < NROWS; i += 256) lsum += logf(g_S[i]);
    int np = 0;
    for (int i = tid; i < BATCH; i += 256) np += (target[i] == 1);
    redf[tid] = lsum; redi[tid] = np;
    __syncthreads();
    for (int s = 128; s; s >>= 1) {
        if (tid < s) { redf[tid] += redf[tid + s]; redi[tid] += redi[tid + s]; }
        __syncthreads();
    }
    if (tid == 0) {
        float logsum = redf[0];
        float n_pos = fmaxf(1.0f, (float)redi[0]);
        float n_unl = fmaxf(1.0f, (float)(BATCH - redi[0]));
        float nt = (logsum - g_acc[6]) / (float)NROWS;

        float li, lj;
        {
            float prisk = PRIOR_PRIME / n_pos * g_acc[0];
            float nrisk = (1.0f - PRIOR_PRIME) / (n_unl * (1.0f - PRIOR)) * g_acc[2]
                        - (1.0f - PRIOR_PRIME) * PRIOR / (n_pos * (1.0f - PRIOR)) * g_acc[1];
            li = (nrisk < 0.0f) ? -nrisk : (prisk + nrisk);
        }
        {
            float prisk = PRIOR_PRIME / n_pos * g_acc[3];
            float nrisk = (1.0f - PRIOR_PRIME) / (n_unl * (1.0f - PRIOR)) * g_acc[5]
                        - (1.0f - PRIOR_PRIME) * PRIOR / (n_pos * (1.0f - PRIOR)) * g_acc[4];
            lj = (nrisk < 0.0f) ? -nrisk : (prisk + nrisk);
        }
        float w = w_onnpu[0];
        out[0] = w * 0.5f * (li + lj) + (1.0f - w) * nt;
    }
}

// ---------------- launch -----------------------------------------------------
extern "C" void kernel_launch(void* const* d_in, const int* in_sizes, int n_in,
                              void* d_out, int out_size) {
    const float* h_i = (const float*)d_in[0];
    const float* h_j = (const float*)d_in[1];
    const float* z_i = (const float*)d_in[2];
    const float* z_j = (const float*)d_in[3];
    const int*   tgt = (const int*)  d_in[4];
    const float* W   = (const float*)d_in[5];
    const float* b   = (const float*)d_in[6];
    const float* wgt = (const float*)d_in[7];
    float* out = (float*)d_out;

    init_kernel<<<32, 256>>>();
    pu_kernel<<<1024, 256>>>(h_i, h_j, W, b, tgt);   // 8192 warps
    norm_kernel<<<1024, 256>>>(z_i, z_j);            // 8192 warps
    pos_kernel<<<1024, 256>>>();

    static int smem_set = 0;
    const int SIM_SMEM = (2 * TDIM * ZDIM + 8 * TDIM) * (int)sizeof(float); // 135168
    if (!smem_set) {
        cudaFuncSetAttribute(sim_kernel,
                             cudaFuncAttributeMaxDynamicSharedMemorySize, SIM_SMEM);
        smem_set = 1;
    }
    sim_kernel<<<dim3(NTILES, NTILES), 256, SIM_SMEM>>>();

    final_kernel<<<1, 256>>>(tgt, wgt, out);
}

// round 3
// speedup vs baseline: 3.0680x; 3.0680x over previous
#include <cuda_runtime.h>
#include <cuda_bf16.h>
#include <stdint.h>
#include <math.h>

#define BATCH   4096
#define LATENT  2048
#define ZDIM    128
#define NROWS   8192
#define TDIM    128
#define NTILES  64
#define TEMP_INV 2.0f
#define PRIOR        0.3f
#define PRIOR_PRIME  0.5f

// ---------------- scratch ----------------------------------------------------
__device__ __nv_bfloat16 g_zb[NROWS * ZDIM];  // normalized z, bf16
__device__ float g_S[NROWS];                  // per-row sum exp(sim), diag excl
__device__ float g_acc[8];                    // 0..2 h_i PU sums, 3..5 h_j, 6 pos

// ---------------- init --------------------------------------------------------
__global__ void init_kernel() {
    int i = blockIdx.x * blockDim.x + threadIdx.x;
    if (i < NROWS) g_S[i] = 0.0f;
    if (i < 8) g_acc[i] = 0.0f;
}

// ---------------- PU branch ---------------------------------------------------
__global__ void pu_kernel(const float* __restrict__ h_i,
                          const float* __restrict__ h_j,
                          const float* __restrict__ W,
                          const float* __restrict__ b,
                          const int*   __restrict__ target) {
    int gw   = (blockIdx.x * blockDim.x + threadIdx.x) >> 5;
    int lane = threadIdx.x & 31;
    if (gw >= 2 * BATCH) return;
    bool is_i = (gw < BATCH);
    int row = is_i ? gw : gw - BATCH;
    const float4* hv = (const float4*)((is_i ? h_i : h_j) + (size_t)row * LATENT);
    const float4* wv = (const float4*)W;

    float acc = 0.0f;
#pragma unroll
    for (int it = 0; it < LATENT / 128; ++it) {
        float4 a = hv[lane + it * 32];
        float4 w = wv[lane + it * 32];
        acc += a.x * w.x + a.y * w.y + a.z * w.z + a.w * w.w;
    }
#pragma unroll
    for (int m = 16; m; m >>= 1) acc += __shfl_xor_sync(0xffffffffu, acc, m);

    if (lane == 0) {
        float logit = acc + b[0];
        int t = target[row];
        int base = is_i ? 0 : 3;
        float sig_neg = 1.0f / (1.0f + __expf(logit));
        float sig_pos = 1.0f / (1.0f + __expf(-logit));
        if (t == 1) {
            atomicAdd(&g_acc[base + 0], sig_neg);
            atomicAdd(&g_acc[base + 1], sig_pos);
        } else {
            atomicAdd(&g_acc[base + 2], sig_pos);
        }
    }
}

// ---------------- normalize -> bf16 ------------------------------------------
__global__ void norm_kernel(const float* __restrict__ z_i,
                            const float* __restrict__ z_j) {
    int gw   = (blockIdx.x * blockDim.x + threadIdx.x) >> 5;
    int lane = threadIdx.x & 31;
    if (gw >= NROWS) return;
    const float* z = (gw < BATCH) ? (z_i + (size_t)gw * ZDIM)
                                  : (z_j + (size_t)(gw - BATCH) * ZDIM);
    float4 v = ((const float4*)z)[lane];
    float ss = v.x * v.x + v.y * v.y + v.z * v.z + v.w * v.w;
#pragma unroll
    for (int m = 16; m; m >>= 1) ss += __shfl_xor_sync(0xffffffffu, ss, m);
    float scale = 1.0f / fmaxf(sqrtf(ss), 1e-8f);
    __nv_bfloat162 h0 = __floats2bfloat162_rn(v.x * scale, v.y * scale);
    __nv_bfloat162 h1 = __floats2bfloat162_rn(v.z * scale, v.w * scale);
    __nv_bfloat162* o = (__nv_bfloat162*)(g_zb + (size_t)gw * ZDIM);
    o[lane * 2]     = h0;
    o[lane * 2 + 1] = h1;
}

// ---------------- MMA helpers -------------------------------------------------
__device__ __forceinline__ void ldmx4(uint32_t& r0, uint32_t& r1,
                                      uint32_t& r2, uint32_t& r3, uint32_t addr) {
    asm volatile("ldmatrix.sync.aligned.m8n8.x4.shared.b16 {%0,%1,%2,%3}, [%4];"
                 : "=r"(r0), "=r"(r1), "=r"(r2), "=r"(r3) : "r"(addr));
}
__device__ __forceinline__ void mma16816(float* d, const uint32_t* a,
                                         uint32_t b0, uint32_t b1) {
    asm volatile("mma.sync.aligned.m16n8k16.row.col.f32.bf16.bf16.f32 "
                 "{%0,%1,%2,%3}, {%4,%5,%6,%7}, {%8,%9}, {%0,%1,%2,%3};"
                 : "+f"(d[0]), "+f"(d[1]), "+f"(d[2]), "+f"(d[3])
                 : "r"(a[0]), "r"(a[1]), "r"(a[2]), "r"(a[3]), "r"(b0), "r"(b1));
}

// ---------------- similarity kernel (bf16 HMMA) -------------------------------
// 128x128 tile per block, K=128 in smem (XOR swizzle on 16B chunks).
// 8 warps: 2(M) x 4(N), each warp 64x32 via 4x4 m16n8k16 atoms, 8 K-steps.
__global__ __launch_bounds__(256)
void sim_kernel() {
    int bi = blockIdx.y, bj = blockIdx.x;
    if (bj < bi) return;

    extern __shared__ unsigned char smem[];
    __nv_bfloat16* As = (__nv_bfloat16*)smem;            // 32 KB
    __nv_bfloat16* Bs = (__nv_bfloat16*)(smem + 32768);  // 32 KB
    float* rowS = (float*)(smem + 65536);                // 128
    float* colS = rowS + 128;                            // 128
    float* posS = colS + 128;                            // 1

    int tid  = threadIdx.x;
    int lane = tid & 31, wid = tid >> 5;
    int wm = wid >> 2, wn = wid & 3;
    int rowbase = bi * TDIM, colbase = bj * TDIM;
    bool diag    = (bi == bj);
    bool has_pos = (bj == (bi ^ 32));

    if (tid < 128) rowS[tid] = 0.0f;
    else           colS[tid - 128] = 0.0f;
    if (tid == 0)  posS[0] = 0.0f;

    // cooperative smem fill, 16B chunks, swizzle: chunk c -> c ^ (row & 7)
    const uint4* Z = (const uint4*)g_zb;   // 16 uint4 per 128-bf16 row
    uint4* A4 = (uint4*)As;
    uint4* B4 = (uint4*)Bs;
#pragma unroll
    for (int l = 0; l < 8; ++l) {
        int idx = tid + l * 256;           // 0..2047
        int r = idx >> 4, c = idx & 15;
        int cs = c ^ (r & 7);
        A4[r * 16 + cs] = Z[(rowbase + r) * 16 + c];
        B4[r * 16 + cs] = Z[(colbase + r) * 16 + c];
    }
    __syncthreads();

    uint32_t Abase = (uint32_t)__cvta_generic_to_shared(As);
    uint32_t Bbase = (uint32_t)__cvta_generic_to_shared(Bs);

    // per-lane ldmatrix row/chunk pattern
    int lr = (lane & 7) + ((lane >> 3) & 1) * 8;   // row offset within 16
    int lh = lane >> 4;                            // chunk offset (0/1)
    int key = lane & 7;                            // swizzle key (= row & 7)

    int rowA[4], rowB[2];
#pragma unroll
    for (int am = 0; am < 4; ++am) rowA[am] = (wm * 64 + am * 16 + lr) * 16;
#pragma unroll
    for (int p = 0; p < 2; ++p)    rowB[p] = (wn * 32 + p * 16 + lr) * 16;

    float acc[4][4][4];
#pragma unroll
    for (int am = 0; am < 4; ++am)
#pragma unroll
        for (int an = 0; an < 4; ++an)
#pragma unroll
            for (int k = 0; k < 4; ++k) acc[am][an][k] = 0.0f;

#pragma unroll
    for (int ks = 0; ks < 8; ++ks) {
        int c = (2 * ks + lh) ^ key;
        uint32_t a[4][4];
        uint32_t bq[2][4];
#pragma unroll
        for (int am = 0; am < 4; ++am)
            ldmx4(a[am][0], a[am][1], a[am][2], a[am][3],
                  Abase + ((rowA[am] + c) << 4));
#pragma unroll
        for (int p = 0; p < 2; ++p)
            ldmx4(bq[p][0], bq[p][1], bq[p][2], bq[p][3],
                  Bbase + ((rowB[p] + c) << 4));
        // an = 2p   -> {bq[p][0], bq[p][2]};  an = 2p+1 -> {bq[p][1], bq[p][3]}
#pragma unroll
        for (int am = 0; am < 4; ++am) {
#pragma unroll
            for (int p = 0; p < 2; ++p) {
                mma16816(acc[am][2 * p],     a[am], bq[p][0], bq[p][2]);
                mma16816(acc[am][2 * p + 1], a[am], bq[p][1], bq[p][3]);
            }
        }
    }

    // epilogue: exp, row/col partial sums, pos extraction
    int qr = lane >> 2, qc = lane & 3;
    float rs[8], cs[8];
#pragma unroll
    for (int i = 0; i < 8; ++i) { rs[i] = 0.0f; cs[i] = 0.0f; }
    float pos = 0.0f;

#pragma unroll
    for (int am = 0; am < 4; ++am) {
        int r0l = wm * 64 + am * 16 + qr;
#pragma unroll
        for (int an = 0; an < 4; ++an) {
            int c0l = wn * 32 + an * 8 + 2 * qc;
#pragma unroll
            for (int k = 0; k < 4; ++k) {
                int rl = r0l + (k >> 1) * 8;
                int cl = c0l + (k & 1);
                float v = acc[am][an][k] * TEMP_INV;
                float e = __expf(v);
                if (diag && rl == cl) e = 0.0f;      // exclude self
                rs[am * 2 + (k >> 1)] += e;
                cs[an * 2 + (k & 1)]  += e;
                if (has_pos && rl == cl) pos += v;   // positive pair logit
            }
        }
    }

    // row partials: reduce over qc (cols within warp), then smem atomics
#pragma unroll
    for (int i = 0; i < 8; ++i) {
        rs[i] += __shfl_xor_sync(0xffffffffu, rs[i], 1);
        rs[i] += __shfl_xor_sync(0xffffffffu, rs[i], 2);
    }
    if (qc == 0) {
#pragma unroll
        for (int i = 0; i < 8; ++i)
            atomicAdd(&rowS[wm * 64 + (i >> 1) * 16 + qr + (i & 1) * 8], rs[i]);
    }
    // col partials: reduce over qr
#pragma unroll
    for (int i = 0; i < 8; ++i) {
        cs[i] += __shfl_xor_sync(0xffffffffu, cs[i], 4);
        cs[i] += __shfl_xor_sync(0xffffffffu, cs[i], 8);
        cs[i] += __shfl_xor_sync(0xffffffffu, cs[i], 16);
    }
    if (lane < 4) {
#pragma unroll
        for (int i = 0; i < 8; ++i)
            atomicAdd(&colS[wn * 32 + (i >> 1) * 8 + 2 * qc + (i & 1)], cs[i]);
    }
    if (has_pos) {
#pragma unroll
        for (int m = 16; m; m >>= 1) pos += __shfl_xor_sync(0xffffffffu, pos, m);
        if (lane == 0) atomicAdd(posS, pos);
    }
    __syncthreads();

    if (tid < 128) atomicAdd(&g_S[rowbase + tid], rowS[tid]);
    else if (!diag) atomicAdd(&g_S[colbase + tid - 128], colS[tid - 128]);
    if (has_pos && tid == 0) atomicAdd(&g_acc[6], posS[0] * 2.0f);  // both rows of pair
}

// ---------------- finalize ----------------------------------------------------
__global__ void final_kernel(const int* __restrict__ target,
                             const float* __restrict__ w_onnpu,
                             float* __restrict__ out) {
    __shared__ float redf[256];
    __shared__ int   redi[256];
    int tid = threadIdx.x;
    float lsum = 0.0f;
    for (int i = tid; i < NROWS; i += 256) lsum += logf(g_S[i]);
    int np = 0;
    for (int i = tid; i < BATCH; i += 256) np += (target[i] == 1);
    redf[tid] = lsum; redi[tid] = np;
    __syncthreads();
    for (int s = 128; s; s >>= 1) {
        if (tid < s) { redf[tid] += redf[tid + s]; redi[tid] += redi[tid + s]; }
        __syncthreads();
    }
    if (tid == 0) {
        float logsum = redf[0];
        float n_pos = fmaxf(1.0f, (float)redi[0]);
        float n_unl = fmaxf(1.0f, (float)(BATCH - redi[0]));
        float nt = (logsum - g_acc[6]) / (float)NROWS;

        float li, lj;
        {
            float prisk = PRIOR_PRIME / n_pos * g_acc[0];
            float nrisk = (1.0f - PRIOR_PRIME) / (n_unl * (1.0f - PRIOR)) * g_acc[2]
                        - (1.0f - PRIOR_PRIME) * PRIOR / (n_pos * (1.0f - PRIOR)) * g_acc[1];
            li = (nrisk < 0.0f) ? -nrisk : (prisk + nrisk);
        }
        {
            float prisk = PRIOR_PRIME / n_pos * g_acc[3];
            float nrisk = (1.0f - PRIOR_PRIME) / (n_unl * (1.0f - PRIOR)) * g_acc[5]
                        - (1.0f - PRIOR_PRIME) * PRIOR / (n_pos * (1.0f - PRIOR)) * g_acc[4];
            lj = (nrisk < 0.0f) ? -nrisk : (prisk + nrisk);
        }
        float w = w_onnpu[0];
        out[0] = w * 0.5f * (li + lj) + (1.0f - w) * nt;
    }
}

// ---------------- launch ------------------------------------------------------
extern "C" void kernel_launch(void* const* d_in, const int* in_sizes, int n_in,
                              void* d_out, int out_size) {
    const float* h_i = (const float*)d_in[0];
    const float* h_j = (const float*)d_in[1];
    const float* z_i = (const float*)d_in[2];
    const float* z_j = (const float*)d_in[3];
    const int*   tgt = (const int*)  d_in[4];
    const float* W   = (const float*)d_in[5];
    const float* b   = (const float*)d_in[6];
    const float* wgt = (const float*)d_in[7];
    float* out = (float*)d_out;

    init_kernel<<<32, 256>>>();
    pu_kernel<<<1024, 256>>>(h_i, h_j, W, b, tgt);
    norm_kernel<<<1024, 256>>>(z_i, z_j);

    static int smem_set = 0;
    const int SIM_SMEM = 65536 + (128 + 128 + 1) * (int)sizeof(float);  // 66564
    if (!smem_set) {
        cudaFuncSetAttribute(sim_kernel,
                             cudaFuncAttributeMaxDynamicSharedMemorySize, SIM_SMEM);
        smem_set = 1;
    }
    sim_kernel<<<dim3(NTILES, NTILES), 256, SIM_SMEM>>>();

    final_kernel<<<1, 256>>>(tgt, wgt, out);
}

// round 5
// speedup vs baseline: 3.3142x; 1.0802x over previous
#include <cuda_runtime.h>
#include <cuda_bf16.h>
#include <stdint.h>
#include <math.h>

#define BATCH   4096
#define LATENT  2048
#define ZDIM    128
#define NROWS   8192
#define TDIM    128
#define NTILES  64
#define NPAIRS  2080          // 64*65/2 upper-triangular tiles
#define TEMP_INV 2.0f
#define PRIOR        0.3f
#define PRIOR_PRIME  0.5f

// ---------------- scratch ----------------------------------------------------
__device__ __nv_bfloat16 g_zb[NROWS * ZDIM];  // normalized z, bf16
__device__ float g_S[NROWS];                  // per-row sum exp(sim), diag excl
__device__ float g_acc[8];                    // 0..2 h_i PU, 3..5 h_j, 6 pos

// ---------------- init --------------------------------------------------------
__global__ void init_kernel() {
    int i = blockIdx.x * blockDim.x + threadIdx.x;
    if (i < NROWS) g_S[i] = 0.0f;
    if (i < 8) g_acc[i] = 0.0f;
}

// ---------------- prep: PU logits + z normalize (merged) ----------------------
__global__ void prep_kernel(const float* __restrict__ h_i,
                            const float* __restrict__ h_j,
                            const float* __restrict__ z_i,
                            const float* __restrict__ z_j,
                            const float* __restrict__ W,
                            const float* __restrict__ b,
                            const int*   __restrict__ target) {
    int bid  = blockIdx.x;
    int wid  = threadIdx.x >> 5;
    int lane = threadIdx.x & 31;

    if (bid < 1024) {
        int gw = bid * 8 + wid;               // 0..8191
        bool is_i = (gw < BATCH);
        int row = is_i ? gw : gw - BATCH;
        const float4* hv = (const float4*)((is_i ? h_i : h_j) + (size_t)row * LATENT);
        const float4* wv = (const float4*)W;
        float acc = 0.0f;
#pragma unroll
        for (int it = 0; it < LATENT / 128; ++it) {
            float4 a = hv[lane + it * 32];
            float4 w = wv[lane + it * 32];
            acc += a.x * w.x + a.y * w.y + a.z * w.z + a.w * w.w;
        }
#pragma unroll
        for (int m = 16; m; m >>= 1) acc += __shfl_xor_sync(0xffffffffu, acc, m);
        if (lane == 0) {
            float logit = acc + b[0];
            int t = target[row];
            int base = is_i ? 0 : 3;
            float sig_neg = 1.0f / (1.0f + __expf(logit));
            float sig_pos = 1.0f / (1.0f + __expf(-logit));
            if (t == 1) {
                atomicAdd(&g_acc[base + 0], sig_neg);
                atomicAdd(&g_acc[base + 1], sig_pos);
            } else {
                atomicAdd(&g_acc[base + 2], sig_pos);
            }
        }
    } else {
        int gw = (bid - 1024) * 8 + wid;      // 0..8191
        const float* z = (gw < BATCH) ? (z_i + (size_t)gw * ZDIM)
                                      : (z_j + (size_t)(gw - BATCH) * ZDIM);
        float4 v = ((const float4*)z)[lane];
        float ss = v.x * v.x + v.y * v.y + v.z * v.z + v.w * v.w;
#pragma unroll
        for (int m = 16; m; m >>= 1) ss += __shfl_xor_sync(0xffffffffu, ss, m);
        float scale = 1.0f / fmaxf(sqrtf(ss), 1e-8f);
        __nv_bfloat162 p0 = __floats2bfloat162_rn(v.x * scale, v.y * scale);
        __nv_bfloat162 p1 = __floats2bfloat162_rn(v.z * scale, v.w * scale);
        __nv_bfloat162* o = (__nv_bfloat162*)(g_zb + (size_t)gw * ZDIM);
        o[lane * 2]     = p0;
        o[lane * 2 + 1] = p1;
    }
}

// ---------------- MMA helpers -------------------------------------------------
__device__ __forceinline__ void ldmx4(uint32_t& r0, uint32_t& r1,
                                      uint32_t& r2, uint32_t& r3, uint32_t addr) {
    asm volatile("ldmatrix.sync.aligned.m8n8.x4.shared.b16 {%0,%1,%2,%3}, [%4];"
                 : "=r"(r0), "=r"(r1), "=r"(r2), "=r"(r3) : "r"(addr));
}
__device__ __forceinline__ void mma16816(float* d, const uint32_t* a,
                                         uint32_t b0, uint32_t b1) {
    asm volatile("mma.sync.aligned.m16n8k16.row.col.f32.bf16.bf16.f32 "
                 "{%0,%1,%2,%3}, {%4,%5,%6,%7}, {%8,%9}, {%0,%1,%2,%3};"
                 : "+f"(d[0]), "+f"(d[1]), "+f"(d[2]), "+f"(d[3])
                 : "r"(a[0]), "r"(a[1]), "r"(a[2]), "r"(a[3]), "r"(b0), "r"(b1));
}

// ---------------- similarity kernel (bf16 HMMA, 64x64 warp tiles) -------------
// 1 upper-triangular 128x128 tile per CTA, 128 threads = 4 warps in 2x2.
// Each warp: 64x64 via 4(M) x 8(N) m16n8k16 atoms, 8 K-steps, K=128 in smem.
__global__ __launch_bounds__(128)
void sim_kernel() {
    extern __shared__ unsigned char smem[];
    __nv_bfloat16* As = (__nv_bfloat16*)smem;            // 32 KB
    __nv_bfloat16* Bs = (__nv_bfloat16*)(smem + 32768);  // 32 KB
    float* rowS = (float*)(smem + 65536);                // 128
    float* colS = rowS + 128;                            // 128
    float* posS = colS + 128;                            // 1

    int tid  = threadIdx.x;
    int lane = tid & 31, wid = tid >> 5;
    int wm = wid >> 1, wn = wid & 1;

    // decode upper-triangular tile index
    int t = blockIdx.x;
    int bi = 0, rem = t;
    while (rem >= NTILES - bi) { rem -= NTILES - bi; ++bi; }
    int bj = bi + rem;
    int rowbase = bi * TDIM, colbase = bj * TDIM;
    bool diag    = (bi == bj);
    bool has_pos = (bj == bi + 32);

    if (tid < 128) { rowS[tid] = 0.0f; colS[tid] = 0.0f; }
    if (tid == 0)  posS[0] = 0.0f;

    // cooperative smem fill, 16B chunks, swizzle: chunk c -> c ^ (row & 7)
    const uint4* Z = (const uint4*)g_zb;   // 16 uint4 per 128-bf16 row
    uint4* A4 = (uint4*)As;
    uint4* B4 = (uint4*)Bs;
#pragma unroll
    for (int l = 0; l < 16; ++l) {
        int idx = tid + l * 128;           // 0..2047
        int r = idx >> 4, c = idx & 15;
        int cs = c ^ (r & 7);
        A4[r * 16 + cs] = Z[(rowbase + r) * 16 + c];
        B4[r * 16 + cs] = Z[(colbase + r) * 16 + c];
    }
    __syncthreads();

    uint32_t Abase = (uint32_t)__cvta_generic_to_shared(As);
    uint32_t Bbase = (uint32_t)__cvta_generic_to_shared(Bs);

    // per-lane ldmatrix row/chunk pattern
    int lr = (lane & 7) + ((lane >> 3) & 1) * 8;   // row offset within 16
    int lh = lane >> 4;                            // chunk offset (0/1)
    int key = lane & 7;                            // swizzle key

    int rowA[4], rowB[4];
#pragma unroll
    for (int am = 0; am < 4; ++am) rowA[am] = (wm * 64 + am * 16 + lr) * 16;
#pragma unroll
    for (int p = 0; p < 4; ++p)    rowB[p] = (wn * 64 + p * 16 + lr) * 16;

    float acc[4][8][4];
#pragma unroll
    for (int am = 0; am < 4; ++am)
#pragma unroll
        for (int an = 0; an < 8; ++an)
#pragma unroll
            for (int k = 0; k < 4; ++k) acc[am][an][k] = 0.0f;

#pragma unroll
    for (int ks = 0; ks < 8; ++ks) {
        int c = (2 * ks + lh) ^ key;
        uint32_t a[4][4];
        uint32_t bq[4][4];
#pragma unroll
        for (int am = 0; am < 4; ++am)
            ldmx4(a[am][0], a[am][1], a[am][2], a[am][3],
                  Abase + ((rowA[am] + c) << 4));
#pragma unroll
        for (int p = 0; p < 4; ++p)
            ldmx4(bq[p][0], bq[p][1], bq[p][2], bq[p][3],
                  Bbase + ((rowB[p] + c) << 4));
#pragma unroll
        for (int am = 0; am < 4; ++am) {
#pragma unroll
            for (int p = 0; p < 4; ++p) {
                mma16816(acc[am][2 * p],     a[am], bq[p][0], bq[p][2]);
                mma16816(acc[am][2 * p + 1], a[am], bq[p][1], bq[p][3]);
            }
        }
    }

    // epilogue: exp, row/col partial sums, pos extraction
    int qr = lane >> 2, qc = lane & 3;
    float rs[8], cs[16];
#pragma unroll
    for (int i = 0; i < 8; ++i)  rs[i] = 0.0f;
#pragma unroll
    for (int i = 0; i < 16; ++i) cs[i] = 0.0f;
    float pos = 0.0f;

#pragma unroll
    for (int am = 0; am < 4; ++am) {
        int r0l = wm * 64 + am * 16 + qr;
#pragma unroll
        for (int an = 0; an < 8; ++an) {
            int c0l = wn * 64 + an * 8 + 2 * qc;
#pragma unroll
            for (int k = 0; k < 4; ++k) {
                int rl = r0l + (k >> 1) * 8;
                int cl = c0l + (k & 1);
                float v = acc[am][an][k] * TEMP_INV;
                float e = __expf(v);
                if (diag && rl == cl) e = 0.0f;      // exclude self
                rs[am * 2 + (k >> 1)] += e;
                cs[an * 2 + (k & 1)]  += e;
                if (has_pos && rl == cl) pos += v;   // positive pair logit
            }
        }
    }

    // row partials: reduce over qc, then smem atomics
#pragma unroll
    for (int i = 0; i < 8; ++i) {
        rs[i] += __shfl_xor_sync(0xffffffffu, rs[i], 1);
        rs[i] += __shfl_xor_sync(0xffffffffu, rs[i], 2);
    }
    if (qc == 0) {
#pragma unroll
        for (int i = 0; i < 8; ++i)
            atomicAdd(&rowS[wm * 64 + (i >> 1) * 16 + qr + (i & 1) * 8], rs[i]);
    }
    // col partials: reduce over qr
#pragma unroll
    for (int i = 0; i < 16; ++i) {
        cs[i] += __shfl_xor_sync(0xffffffffu, cs[i], 4);
        cs[i] += __shfl_xor_sync(0xffffffffu, cs[i], 8);
        cs[i] += __shfl_xor_sync(0xffffffffu, cs[i], 16);
    }
    if (lane < 4) {
#pragma unroll
        for (int i = 0; i < 16; ++i)
            atomicAdd(&colS[wn * 64 + (i >> 1) * 8 + 2 * lane + (i & 1)], cs[i]);
    }
    if (has_pos) {
#pragma unroll
        for (int m = 16; m; m >>= 1) pos += __shfl_xor_sync(0xffffffffu, pos, m);
        if (lane == 0) atomicAdd(posS, pos);
    }
    __syncthreads();

    if (tid < 128) {
        atomicAdd(&g_S[rowbase + tid], rowS[tid]);
        if (!diag) atomicAdd(&g_S[colbase + tid], colS[tid]);
    }
    if (has_pos && tid == 0) atomicAdd(&g_acc[6], posS[0] * 2.0f);
}

// ---------------- finalize ----------------------------------------------------
__global__ void final_kernel(const int* __restrict__ target,
                             const float* __restrict__ w_onnpu,
                             float* __restrict__ out) {
    __shared__ float redf[1024];
    __shared__ int   redi[1024];
    int tid = threadIdx.x;
    float lsum = 0.0f;
    for (int i = tid; i < NROWS; i += 1024) lsum += __logf(g_S[i]);
    int np = 0;
    for (int i = tid; i < BATCH; i += 1024) np += (target[i] == 1);
    redf[tid] = lsum; redi[tid] = np;
    __syncthreads();
    for (int s = 512; s; s >>= 1) {
        if (tid < s) { redf[tid] += redf[tid + s]; redi[tid] += redi[tid + s]; }
        __syncthreads();
    }
    if (tid == 0) {
        float logsum = redf[0];
        float n_pos = fmaxf(1.0f, (float)redi[0]);
        float n_unl = fmaxf(1.0f, (float)(BATCH - redi[0]));
        float nt = (logsum - g_acc[6]) / (float)NROWS;

        float li, lj;
        {
            float prisk = PRIOR_PRIME / n_pos * g_acc[0];
            float nrisk = (1.0f - PRIOR_PRIME) / (n_unl * (1.0f - PRIOR)) * g_acc[2]
                        - (1.0f - PRIOR_PRIME) * PRIOR / (n_pos * (1.0f - PRIOR)) * g_acc[1];
            li = (nrisk < 0.0f) ? -nrisk : (prisk + nrisk);
        }
        {
            float prisk = PRIOR_PRIME / n_pos * g_acc[3];
            float nrisk = (1.0f - PRIOR_PRIME) / (n_unl * (1.0f - PRIOR)) * g_acc[5]
                        - (1.0f - PRIOR_PRIME) * PRIOR / (n_pos * (1.0f - PRIOR)) * g_acc[4];
            lj = (nrisk < 0.0f) ? -nrisk : (prisk + nrisk);
        }
        float w = w_onnpu[0];
        out[0] = w * 0.5f * (li + lj) + (1.0f - w) * nt;
    }
}

// ---------------- launch ------------------------------------------------------
extern "C" void kernel_launch(void* const* d_in, const int* in_sizes, int n_in,
                              void* d_out, int out_size) {
    const float* h_i = (const float*)d_in[0];
    const float* h_j = (const float*)d_in[1];
    const float* z_i = (const float*)d_in[2];
    const float* z_j = (const float*)d_in[3];
    const int*   tgt = (const int*)  d_in[4];
    const float* W   = (const float*)d_in[5];
    const float* b   = (const float*)d_in[6];
    const float* wgt = (const float*)d_in[7];
    float* out = (float*)d_out;

    static int smem_set = 0;
    const int SIM_SMEM = 65536 + (128 + 128 + 1) * (int)sizeof(float);  // 66564
    if (!smem_set) {
        cudaFuncSetAttribute(sim_kernel,
                             cudaFuncAttributeMaxDynamicSharedMemorySize, SIM_SMEM);
        smem_set = 1;
    }

    init_kernel<<<32, 256>>>();
    prep_kernel<<<2048, 256>>>(h_i, h_j, z_i, z_j, W, b, tgt);
    sim_kernel<<<NPAIRS, 128, SIM_SMEM>>>();
    final_kernel<<<1, 1024>>>(tgt, wgt, out);
}

// round 6
// speedup vs baseline: 3.8250x; 1.1541x over previous
#include <cuda_runtime.h>
#include <cuda_bf16.h>
#include <stdint.h>
#include <math.h>

#define BATCH   4096
#define LATENT  2048
#define ZDIM    128
#define NROWS   8192
#define TDIM    128
#define NTILES  64
#define NPAIRS  2080          // 64*65/2 upper-triangular tiles
#define TEMP_INV 2.0f
#define PRIOR        0.3f
#define PRIOR_PRIME  0.5f

// ---------------- scratch (zero-init at load; final_kernel restores zeros) ---
__device__ __nv_bfloat16 g_zb[NROWS * ZDIM];  // normalized z, bf16
__device__ float    g_S[NROWS];               // per-row sum exp(sim), diag excl
__device__ float    g_acc[8];                 // 0..2 h_i PU, 3..5 h_j, 6 pos, 7 logsum
__device__ int      g_np = 0;                 // positive count
__device__ unsigned g_ctr = 0;                // final arrival counter

// ---------------- prep: PU logits + z normalize (merged) ----------------------
__global__ void prep_kernel(const float* __restrict__ h_i,
                            const float* __restrict__ h_j,
                            const float* __restrict__ z_i,
                            const float* __restrict__ z_j,
                            const float* __restrict__ W,
                            const float* __restrict__ b,
                            const int*   __restrict__ target) {
    int bid  = blockIdx.x;
    int wid  = threadIdx.x >> 5;
    int lane = threadIdx.x & 31;

    if (bid < 1024) {
        int gw = bid * 8 + wid;               // 0..8191
        bool is_i = (gw < BATCH);
        int row = is_i ? gw : gw - BATCH;
        const float4* hv = (const float4*)((is_i ? h_i : h_j) + (size_t)row * LATENT);
        const float4* wv = (const float4*)W;
        float acc = 0.0f;
#pragma unroll
        for (int it = 0; it < LATENT / 128; ++it) {
            float4 a = hv[lane + it * 32];
            float4 w = wv[lane + it * 32];
            acc += a.x * w.x + a.y * w.y + a.z * w.z + a.w * w.w;
        }
#pragma unroll
        for (int m = 16; m; m >>= 1) acc += __shfl_xor_sync(0xffffffffu, acc, m);
        if (lane == 0) {
            float logit = acc + b[0];
            int t = target[row];
            int base = is_i ? 0 : 3;
            float sig_neg = 1.0f / (1.0f + __expf(logit));
            float sig_pos = 1.0f / (1.0f + __expf(-logit));
            if (t == 1) {
                atomicAdd(&g_acc[base + 0], sig_neg);
                atomicAdd(&g_acc[base + 1], sig_pos);
            } else {
                atomicAdd(&g_acc[base + 2], sig_pos);
            }
        }
    } else {
        int gw = (bid - 1024) * 8 + wid;      // 0..8191
        const float* z = (gw < BATCH) ? (z_i + (size_t)gw * ZDIM)
                                      : (z_j + (size_t)(gw - BATCH) * ZDIM);
        float4 v = ((const float4*)z)[lane];
        float ss = v.x * v.x + v.y * v.y + v.z * v.z + v.w * v.w;
#pragma unroll
        for (int m = 16; m; m >>= 1) ss += __shfl_xor_sync(0xffffffffu, ss, m);
        float scale = 1.0f / fmaxf(sqrtf(ss), 1e-8f);
        __nv_bfloat162 p0 = __floats2bfloat162_rn(v.x * scale, v.y * scale);
        __nv_bfloat162 p1 = __floats2bfloat162_rn(v.z * scale, v.w * scale);
        __nv_bfloat162* o = (__nv_bfloat162*)(g_zb + (size_t)gw * ZDIM);
        o[lane * 2]     = p0;
        o[lane * 2 + 1] = p1;
    }
}

// ---------------- MMA helpers -------------------------------------------------
__device__ __forceinline__ void ldmx4(uint32_t& r0, uint32_t& r1,
                                      uint32_t& r2, uint32_t& r3, uint32_t addr) {
    asm volatile("ldmatrix.sync.aligned.m8n8.x4.shared.b16 {%0,%1,%2,%3}, [%4];"
                 : "=r"(r0), "=r"(r1), "=r"(r2), "=r"(r3) : "r"(addr));
}
__device__ __forceinline__ void mma16816(float* d, const uint32_t* a,
                                         uint32_t b0, uint32_t b1) {
    asm volatile("mma.sync.aligned.m16n8k16.row.col.f32.bf16.bf16.f32 "
                 "{%0,%1,%2,%3}, {%4,%5,%6,%7}, {%8,%9}, {%0,%1,%2,%3};"
                 : "+f"(d[0]), "+f"(d[1]), "+f"(d[2]), "+f"(d[3])
                 : "r"(a[0]), "r"(a[1]), "r"(a[2]), "r"(a[3]), "r"(b0), "r"(b1));
}
__device__ __forceinline__ void cp16(uint32_t smem_dst, const void* gmem_src) {
    asm volatile("cp.async.cg.shared.global [%0], [%1], 16;"
                 :: "r"(smem_dst), "l"(gmem_src));
}

// ---------------- similarity kernel (bf16 HMMA, 64x64 warp tiles) -------------
__global__ __launch_bounds__(128)
void sim_kernel() {
    extern __shared__ unsigned char smem[];
    __nv_bfloat16* As = (__nv_bfloat16*)smem;            // 32 KB
    __nv_bfloat16* Bs = (__nv_bfloat16*)(smem + 32768);  // 32 KB
    float* rowS = (float*)(smem + 65536);                // 128
    float* colS = rowS + 128;                            // 128
    float* posS = colS + 128;                            // 1

    int tid  = threadIdx.x;
    int lane = tid & 31, wid = tid >> 5;
    int wm = wid >> 1, wn = wid & 1;

    // decode upper-triangular tile index
    int t = blockIdx.x;
    int bi = 0, rem = t;
    while (rem >= NTILES - bi) { rem -= NTILES - bi; ++bi; }
    int bj = bi + rem;
    int rowbase = bi * TDIM, colbase = bj * TDIM;
    bool diag    = (bi == bj);
    bool has_pos = (bj == bi + 32);

    rowS[tid] = 0.0f;
    colS[tid] = 0.0f;
    if (tid == 0) posS[0] = 0.0f;

    // cooperative smem fill via cp.async, 16B chunks, swizzle c -> c ^ (r & 7)
    const uint4* Z = (const uint4*)g_zb;   // 16 uint4 per 128-bf16 row
    uint32_t Abase = (uint32_t)__cvta_generic_to_shared(As);
    uint32_t Bbase = (uint32_t)__cvta_generic_to_shared(Bs);
#pragma unroll
    for (int l = 0; l < 16; ++l) {
        int idx = tid + l * 128;           // 0..2047
        int r = idx >> 4, c = idx & 15;
        int cs = c ^ (r & 7);
        cp16(Abase + (r * 16 + cs) * 16, Z + (rowbase + r) * 16 + c);
        cp16(Bbase + (r * 16 + cs) * 16, Z + (colbase + r) * 16 + c);
    }
    asm volatile("cp.async.commit_group;" ::: "memory");
    asm volatile("cp.async.wait_group 0;" ::: "memory");
    __syncthreads();

    // per-lane ldmatrix row/chunk pattern
    int lr = (lane & 7) + ((lane >> 3) & 1) * 8;   // row offset within 16
    int lh = lane >> 4;                            // chunk offset (0/1)
    int key = lane & 7;                            // swizzle key

    int rowA[4], rowB[4];
#pragma unroll
    for (int am = 0; am < 4; ++am) rowA[am] = (wm * 64 + am * 16 + lr) * 16;
#pragma unroll
    for (int p = 0; p < 4; ++p)    rowB[p] = (wn * 64 + p * 16 + lr) * 16;

    float acc[4][8][4];
#pragma unroll
    for (int am = 0; am < 4; ++am)
#pragma unroll
        for (int an = 0; an < 8; ++an)
#pragma unroll
            for (int k = 0; k < 4; ++k) acc[am][an][k] = 0.0f;

#pragma unroll
    for (int ks = 0; ks < 8; ++ks) {
        int c = (2 * ks + lh) ^ key;
        uint32_t a[4][4];
        uint32_t bq[4][4];
#pragma unroll
        for (int am = 0; am < 4; ++am)
            ldmx4(a[am][0], a[am][1], a[am][2], a[am][3],
                  Abase + ((rowA[am] + c) << 4));
#pragma unroll
        for (int p = 0; p < 4; ++p)
            ldmx4(bq[p][0], bq[p][1], bq[p][2], bq[p][3],
                  Bbase + ((rowB[p] + c) << 4));
#pragma unroll
        for (int am = 0; am < 4; ++am) {
#pragma unroll
            for (int p = 0; p < 4; ++p) {
                mma16816(acc[am][2 * p],     a[am], bq[p][0], bq[p][2]);
                mma16816(acc[am][2 * p + 1], a[am], bq[p][1], bq[p][3]);
            }
        }
    }

    // epilogue: exp, row/col partial sums, pos extraction
    int qr = lane >> 2, qc = lane & 3;
    float rs[8], cs[16];
#pragma unroll
    for (int i = 0; i < 8; ++i)  rs[i] = 0.0f;
#pragma unroll
    for (int i = 0; i < 16; ++i) cs[i] = 0.0f;
    float pos = 0.0f;

#pragma unroll
    for (int am = 0; am < 4; ++am) {
        int r0l = wm * 64 + am * 16 + qr;
#pragma unroll
        for (int an = 0; an < 8; ++an) {
            int c0l = wn * 64 + an * 8 + 2 * qc;
#pragma unroll
            for (int k = 0; k < 4; ++k) {
                int rl = r0l + (k >> 1) * 8;
                int cl = c0l + (k & 1);
                float v = acc[am][an][k] * TEMP_INV;
                float e = __expf(v);
                if (diag && rl == cl) e = 0.0f;      // exclude self
                rs[am * 2 + (k >> 1)] += e;
                cs[an * 2 + (k & 1)]  += e;
                if (has_pos && rl == cl) pos += v;   // positive pair logit
            }
        }
    }

#pragma unroll
    for (int i = 0; i < 8; ++i) {
        rs[i] += __shfl_xor_sync(0xffffffffu, rs[i], 1);
        rs[i] += __shfl_xor_sync(0xffffffffu, rs[i], 2);
    }
    if (qc == 0) {
#pragma unroll
        for (int i = 0; i < 8; ++i)
            atomicAdd(&rowS[wm * 64 + (i >> 1) * 16 + qr + (i & 1) * 8], rs[i]);
    }
#pragma unroll
    for (int i = 0; i < 16; ++i) {
        cs[i] += __shfl_xor_sync(0xffffffffu, cs[i], 4);
        cs[i] += __shfl_xor_sync(0xffffffffu, cs[i], 8);
        cs[i] += __shfl_xor_sync(0xffffffffu, cs[i], 16);
    }
    if (lane < 4) {
#pragma unroll
        for (int i = 0; i < 16; ++i)
            atomicAdd(&colS[wn * 64 + (i >> 1) * 8 + 2 * lane + (i & 1)], cs[i]);
    }
    if (has_pos) {
#pragma unroll
        for (int m = 16; m; m >>= 1) pos += __shfl_xor_sync(0xffffffffu, pos, m);
        if (lane == 0) atomicAdd(posS, pos);
    }
    __syncthreads();

    atomicAdd(&g_S[rowbase + tid], rowS[tid]);
    if (!diag) atomicAdd(&g_S[colbase + tid], colS[tid]);
    if (has_pos && tid == 0) atomicAdd(&g_acc[6], posS[0] * 2.0f);
}

// ---------------- finalize (parallel, single launch, self-resetting) ----------
__global__ void final_kernel(const int* __restrict__ target,
                             const float* __restrict__ w_onnpu,
                             float* __restrict__ out) {
    __shared__ float wsf[4];
    __shared__ int   wsi[4];
    __shared__ int   lastflag;
    int tid  = threadIdx.x;
    int lane = tid & 31, wid = tid >> 5;
    int i = blockIdx.x * 128 + tid;         // 0..8191

    float l = __logf(g_S[i]);
    int np = (i < BATCH) ? (target[i] == 1) : 0;
#pragma unroll
    for (int m = 16; m; m >>= 1) {
        l  += __shfl_xor_sync(0xffffffffu, l, m);
        np += __shfl_xor_sync(0xffffffffu, np, m);
    }
    if (lane == 0) { wsf[wid] = l; wsi[wid] = np; }
    __syncthreads();
    if (tid == 0) {
        float bs = wsf[0] + wsf[1] + wsf[2] + wsf[3];
        int   bn = wsi[0] + wsi[1] + wsi[2] + wsi[3];
        atomicAdd(&g_acc[7], bs);
        if (bn) atomicAdd(&g_np, bn);
        __threadfence();
        unsigned old = atomicInc(&g_ctr, 63u);   // wraps to 0 on last arrival
        lastflag = (old == 63u);
    }
    __syncthreads();
    if (lastflag) {
        // last block: compute result, then restore zero-state for next call
        if (tid == 0) {
            float logsum = g_acc[7];
            float n_pos = fmaxf(1.0f, (float)g_np);
            float n_unl = fmaxf(1.0f, (float)(BATCH - g_np));
            float nt = (logsum - g_acc[6]) / (float)NROWS;
            float li, lj;
            {
                float prisk = PRIOR_PRIME / n_pos * g_acc[0];
                float nrisk = (1.0f - PRIOR_PRIME) / (n_unl * (1.0f - PRIOR)) * g_acc[2]
                            - (1.0f - PRIOR_PRIME) * PRIOR / (n_pos * (1.0f - PRIOR)) * g_acc[1];
                li = (nrisk < 0.0f) ? -nrisk : (prisk + nrisk);
            }
            {
                float prisk = PRIOR_PRIME / n_pos * g_acc[3];
                float nrisk = (1.0f - PRIOR_PRIME) / (n_unl * (1.0f - PRIOR)) * g_acc[5]
                            - (1.0f - PRIOR_PRIME) * PRIOR / (n_pos * (1.0f - PRIOR)) * g_acc[4];
                lj = (nrisk < 0.0f) ? -nrisk : (prisk + nrisk);
            }
            float w = w_onnpu[0];
            out[0] = w * 0.5f * (li + lj) + (1.0f - w) * nt;
            // reset scalars (g_ctr already wrapped to 0)
#pragma unroll
            for (int k = 0; k < 8; ++k) g_acc[k] = 0.0f;
            g_np = 0;
        }
        // reset g_S cooperatively
        for (int k = tid; k < NROWS; k += 128) g_S[k] = 0.0f;
    }
}

// ---------------- launch ------------------------------------------------------
extern "C" void kernel_launch(void* const* d_in, const int* in_sizes, int n_in,
                              void* d_out, int out_size) {
    const float* h_i = (const float*)d_in[0];
    const float* h_j = (const float*)d_in[1];
    const float* z_i = (const float*)d_in[2];
    const float* z_j = (const float*)d_in[3];
    const int*   tgt = (const int*)  d_in[4];
    const float* W   = (const float*)d_in[5];
    const float* b   = (const float*)d_in[6];
    const float* wgt = (const float*)d_in[7];
    float* out = (float*)d_out;

    static int smem_set = 0;
    const int SIM_SMEM = 65536 + (128 + 128 + 1) * (int)sizeof(float);  // 66564
    if (!smem_set) {
        cudaFuncSetAttribute(sim_kernel,
                             cudaFuncAttributeMaxDynamicSharedMemorySize, SIM_SMEM);
        smem_set = 1;
    }

    prep_kernel<<<2048, 256>>>(h_i, h_j, z_i, z_j, W, b, tgt);
    sim_kernel<<<NPAIRS, 128, SIM_SMEM>>>();
    final_kernel<<<64, 128>>>(tgt, wgt, out);
}

// round 7
// speedup vs baseline: 4.8620x; 1.2711x over previous
#include <cuda_runtime.h>
#include <cuda_bf16.h>
#include <stdint.h>
#include <math.h>

#define BATCH   4096
#define LATENT  2048
#define ZDIM    128
#define NROWS   8192
#define TDIM    128
#define NTILES  64
#define NPAIRS  2080          // 64*65/2 upper-triangular tiles
#define TEMP_INV 2.0f
#define PRIOR        0.3f
#define PRIOR_PRIME  0.5f

#define PU_BLOCKS   256       // 32 rows each (128 for h_i, 128 for h_j)
#define ROWS_PER_BLK 32
#define STAGE_ROWS  4
#define STAGE_BYTES (STAGE_ROWS * LATENT * 4)   // 32768
#define N_STAGES    3
#define N_ITERS     (ROWS_PER_BLK / STAGE_ROWS) // 8
#define PREP_SMEM   (N_STAGES * STAGE_BYTES + 256)  // stages + mbars + rowAcc

// ---------------- scratch (zero-init at load; final_kernel restores zeros) ---
__device__ __nv_bfloat16 g_zb[NROWS * ZDIM];  // normalized z, bf16
__device__ float    g_S[NROWS];               // per-row sum exp(sim), diag excl
__device__ float    g_acc[8];                 // 0..2 h_i PU, 3..5 h_j, 6 pos, 7 logsum
__device__ int      g_np = 0;                 // positive count
__device__ unsigned g_ctr = 0;                // final arrival counter

// ---------------- small PTX helpers -------------------------------------------
__device__ __forceinline__ void mb_init(uint32_t mb, uint32_t cnt) {
    asm volatile("mbarrier.init.shared.b64 [%0], %1;" :: "r"(mb), "r"(cnt) : "memory");
}
__device__ __forceinline__ void mb_expect_tx(uint32_t mb, uint32_t bytes) {
    asm volatile("mbarrier.arrive.expect_tx.shared.b64 _, [%0], %1;"
                 :: "r"(mb), "r"(bytes) : "memory");
}
__device__ __forceinline__ void mb_wait(uint32_t mb, uint32_t ph) {
    asm volatile(
        "{\n\t.reg .pred P1;\n\t"
        "WAIT_%=:\n\t"
        "mbarrier.try_wait.parity.acquire.cta.shared::cta.b64 P1, [%0], %1, 0x989680;\n\t"
        "@P1 bra.uni DONE_%=;\n\t"
        "bra.uni WAIT_%=;\n\t"
        "DONE_%=:\n\t}"
        :: "r"(mb), "r"(ph) : "memory");
}
__device__ __forceinline__ void bulk_g2s(uint32_t dst, const void* src,
                                         uint32_t bytes, uint32_t mb) {
    asm volatile("cp.async.bulk.shared::cta.global.mbarrier::complete_tx::bytes "
                 "[%0], [%1], %2, [%3];"
                 :: "r"(dst), "l"(src), "r"(bytes), "r"(mb) : "memory");
}

// ---------------- prep: PU via TMA pipeline + z normalize ---------------------
__global__ __launch_bounds__(256)
void prep_kernel(const float* __restrict__ h_i,
                 const float* __restrict__ h_j,
                 const float* __restrict__ z_i,
                 const float* __restrict__ z_j,
                 const float* __restrict__ W,
                 const float* __restrict__ b,
                 const int*   __restrict__ target) {
    int bid  = blockIdx.x;
    int tid  = threadIdx.x;
    int wid  = tid >> 5;
    int lane = tid & 31;

    if (bid < PU_BLOCKS) {
        // ------- PU branch: stream 32 rows of h through TMA-fed smem ---------
        extern __shared__ unsigned char sm[];
        float* stage = (float*)sm;                           // 3 x 32KB
        uint32_t smbase = (uint32_t)__cvta_generic_to_shared(sm);
        uint32_t mb0 = smbase + N_STAGES * STAGE_BYTES;      // 3 x 8B mbarriers
        float* rowAcc = (float*)(sm + N_STAGES * STAGE_BYTES + 32); // 32 floats

        bool is_i = (bid < 128);
        int r0 = (is_i ? bid : bid - 128) * ROWS_PER_BLK;
        const float* hbase = (is_i ? h_i : h_j) + (size_t)r0 * LATENT;

        // W chunk for this warp's half-row -> registers (loop-invariant)
        int half = wid & 1;
        const float4* wv = (const float4*)W;
        float4 wreg[8];
#pragma unroll
        for (int k = 0; k < 8; ++k) wreg[k] = wv[half * 256 + lane + k * 32];

        if (tid == 0) {
#pragma unroll
            for (int s = 0; s < N_STAGES; ++s) mb_init(mb0 + s * 8, 1);
        }
        if (tid < 32) rowAcc[tid] = 0.0f;
        __syncthreads();

        if (tid == 0) {
            asm volatile("fence.proxy.async.shared::cta;" ::: "memory");
#pragma unroll
            for (int s = 0; s < N_STAGES; ++s) {
                mb_expect_tx(mb0 + s * 8, STAGE_BYTES);
                bulk_g2s(smbase + s * STAGE_BYTES,
                         hbase + (size_t)s * STAGE_ROWS * LATENT,
                         STAGE_BYTES, mb0 + s * 8);
            }
        }

        int row = wid >> 1;   // 0..3 within stage
#pragma unroll
        for (int it = 0; it < N_ITERS; ++it) {
            int s  = it % N_STAGES;
            int ph = (it / N_STAGES) & 1;
            mb_wait(mb0 + s * 8, ph);

            const float4* hrow = (const float4*)(stage + s * (STAGE_BYTES / 4)
                                                 + row * LATENT);
            float acc = 0.0f;
#pragma unroll
            for (int k = 0; k < 8; ++k) {
                float4 a = hrow[half * 256 + lane + k * 32];
                acc += a.x * wreg[k].x + a.y * wreg[k].y +
                       a.z * wreg[k].z + a.w * wreg[k].w;
            }
#pragma unroll
            for (int m = 16; m; m >>= 1) acc += __shfl_xor_sync(0xffffffffu, acc, m);
            if (lane == 0) atomicAdd(&rowAcc[it * STAGE_ROWS + row], acc);

            __syncthreads();   // stage fully consumed by all warps
            if (tid == 0 && it + N_STAGES < N_ITERS) {
                mb_expect_tx(mb0 + s * 8, STAGE_BYTES);
                bulk_g2s(smbase + s * STAGE_BYTES,
                         hbase + (size_t)(it + N_STAGES) * STAGE_ROWS * LATENT,
                         STAGE_BYTES, mb0 + s * 8);
            }
        }
        __syncthreads();

        if (tid < 32) {
            float logit = rowAcc[tid] + b[0];
            int t = target[r0 + tid];
            float sig_neg = 1.0f / (1.0f + __expf(logit));
            float sig_pos = 1.0f / (1.0f + __expf(-logit));
            float ypos    = (t == 1) ? sig_neg : 0.0f;
            float yposinv = (t == 1) ? sig_pos : 0.0f;
            float yunl    = (t == 1) ? 0.0f : sig_pos;
#pragma unroll
            for (int m = 16; m; m >>= 1) {
                ypos    += __shfl_xor_sync(0xffffffffu, ypos, m);
                yposinv += __shfl_xor_sync(0xffffffffu, yposinv, m);
                yunl    += __shfl_xor_sync(0xffffffffu, yunl, m);
            }
            if (lane == 0) {
                int base = is_i ? 0 : 3;
                atomicAdd(&g_acc[base + 0], ypos);
                atomicAdd(&g_acc[base + 1], yposinv);
                atomicAdd(&g_acc[base + 2], yunl);
            }
        }
    } else {
        // ------- normalize branch: one warp per z row ------------------------
        int gw = (bid - PU_BLOCKS) * 8 + wid;     // 0..8191
        const float* z = (gw < BATCH) ? (z_i + (size_t)gw * ZDIM)
                                      : (z_j + (size_t)(gw - BATCH) * ZDIM);
        float4 v = ((const float4*)z)[lane];
        float ss = v.x * v.x + v.y * v.y + v.z * v.z + v.w * v.w;
#pragma unroll
        for (int m = 16; m; m >>= 1) ss += __shfl_xor_sync(0xffffffffu, ss, m);
        float scale = 1.0f / fmaxf(sqrtf(ss), 1e-8f);
        __nv_bfloat162 p0 = __floats2bfloat162_rn(v.x * scale, v.y * scale);
        __nv_bfloat162 p1 = __floats2bfloat162_rn(v.z * scale, v.w * scale);
        __nv_bfloat162* o = (__nv_bfloat162*)(g_zb + (size_t)gw * ZDIM);
        o[lane * 2]     = p0;
        o[lane * 2 + 1] = p1;
    }
}

// ---------------- MMA helpers -------------------------------------------------
__device__ __forceinline__ void ldmx4(uint32_t& r0, uint32_t& r1,
                                      uint32_t& r2, uint32_t& r3, uint32_t addr) {
    asm volatile("ldmatrix.sync.aligned.m8n8.x4.shared.b16 {%0,%1,%2,%3}, [%4];"
                 : "=r"(r0), "=r"(r1), "=r"(r2), "=r"(r3) : "r"(addr));
}
__device__ __forceinline__ void mma16816(float* d, const uint32_t* a,
                                         uint32_t b0, uint32_t b1) {
    asm volatile("mma.sync.aligned.m16n8k16.row.col.f32.bf16.bf16.f32 "
                 "{%0,%1,%2,%3}, {%4,%5,%6,%7}, {%8,%9}, {%0,%1,%2,%3};"
                 : "+f"(d[0]), "+f"(d[1]), "+f"(d[2]), "+f"(d[3])
                 : "r"(a[0]), "r"(a[1]), "r"(a[2]), "r"(a[3]), "r"(b0), "r"(b1));
}
__device__ __forceinline__ void cp16(uint32_t smem_dst, const void* gmem_src) {
    asm volatile("cp.async.cg.shared.global [%0], [%1], 16;"
                 :: "r"(smem_dst), "l"(gmem_src));
}

// ---------------- similarity kernel (bf16 HMMA, 64x64 warp tiles) -------------
__global__ __launch_bounds__(128)
void sim_kernel() {
    extern __shared__ unsigned char smem[];
    __nv_bfloat16* As = (__nv_bfloat16*)smem;            // 32 KB
    __nv_bfloat16* Bs = (__nv_bfloat16*)(smem + 32768);  // 32 KB
    float* rowS = (float*)(smem + 65536);                // 128
    float* colS = rowS + 128;                            // 128
    float* posS = colS + 128;                            // 1

    int tid  = threadIdx.x;
    int lane = tid & 31, wid = tid >> 5;
    int wm = wid >> 1, wn = wid & 1;

    // decode upper-triangular tile index
    int t = blockIdx.x;
    int bi = 0, rem = t;
    while (rem >= NTILES - bi) { rem -= NTILES - bi; ++bi; }
    int bj = bi + rem;
    int rowbase = bi * TDIM, colbase = bj * TDIM;
    bool diag    = (bi == bj);
    bool has_pos = (bj == bi + 32);

    rowS[tid] = 0.0f;
    colS[tid] = 0.0f;
    if (tid == 0) posS[0] = 0.0f;

    // cooperative smem fill via cp.async, 16B chunks, swizzle c -> c ^ (r & 7)
    const uint4* Z = (const uint4*)g_zb;   // 16 uint4 per 128-bf16 row
    uint32_t Abase = (uint32_t)__cvta_generic_to_shared(As);
    uint32_t Bbase = (uint32_t)__cvta_generic_to_shared(Bs);
#pragma unroll
    for (int l = 0; l < 16; ++l) {
        int idx = tid + l * 128;           // 0..2047
        int r = idx >> 4, c = idx & 15;
        int cs = c ^ (r & 7);
        cp16(Abase + (r * 16 + cs) * 16, Z + (rowbase + r) * 16 + c);
        cp16(Bbase + (r * 16 + cs) * 16, Z + (colbase + r) * 16 + c);
    }
    asm volatile("cp.async.commit_group;" ::: "memory");
    asm volatile("cp.async.wait_group 0;" ::: "memory");
    __syncthreads();

    // per-lane ldmatrix row/chunk pattern
    int lr = (lane & 7) + ((lane >> 3) & 1) * 8;   // row offset within 16
    int lh = lane >> 4;                            // chunk offset (0/1)
    int key = lane & 7;                            // swizzle key

    int rowA[4], rowB[4];
#pragma unroll
    for (int am = 0; am < 4; ++am) rowA[am] = (wm * 64 + am * 16 + lr) * 16;
#pragma unroll
    for (int p = 0; p < 4; ++p)    rowB[p] = (wn * 64 + p * 16 + lr) * 16;

    float acc[4][8][4];
#pragma unroll
    for (int am = 0; am < 4; ++am)
#pragma unroll
        for (int an = 0; an < 8; ++an)
#pragma unroll
            for (int k = 0; k < 4; ++k) acc[am][an][k] = 0.0f;

#pragma unroll
    for (int ks = 0; ks < 8; ++ks) {
        int c = (2 * ks + lh) ^ key;
        uint32_t a[4][4];
        uint32_t bq[4][4];
#pragma unroll
        for (int am = 0; am < 4; ++am)
            ldmx4(a[am][0], a[am][1], a[am][2], a[am][3],
                  Abase + ((rowA[am] + c) << 4));
#pragma unroll
        for (int p = 0; p < 4; ++p)
            ldmx4(bq[p][0], bq[p][1], bq[p][2], bq[p][3],
                  Bbase + ((rowB[p] + c) << 4));
#pragma unroll
        for (int am = 0; am < 4; ++am) {
#pragma unroll
            for (int p = 0; p < 4; ++p) {
                mma16816(acc[am][2 * p],     a[am], bq[p][0], bq[p][2]);
                mma16816(acc[am][2 * p + 1], a[am], bq[p][1], bq[p][3]);
            }
        }
    }

    // epilogue: exp, row/col partial sums, pos extraction
    int qr = lane >> 2, qc = lane & 3;
    float rs[8], cs[16];
#pragma unroll
    for (int i = 0; i < 8; ++i)  rs[i] = 0.0f;
#pragma unroll
    for (int i = 0; i < 16; ++i) cs[i] = 0.0f;
    float pos = 0.0f;

#pragma unroll
    for (int am = 0; am < 4; ++am) {
        int r0l = wm * 64 + am * 16 + qr;
#pragma unroll
        for (int an = 0; an < 8; ++an) {
            int c0l = wn * 64 + an * 8 + 2 * qc;
#pragma unroll
            for (int k = 0; k < 4; ++k) {
                int rl = r0l + (k >> 1) * 8;
                int cl = c0l + (k & 1);
                float v = acc[am][an][k] * TEMP_INV;
                float e = __expf(v);
                if (diag && rl == cl) e = 0.0f;      // exclude self
                rs[am * 2 + (k >> 1)] += e;
                cs[an * 2 + (k & 1)]  += e;
                if (has_pos && rl == cl) pos += v;   // positive pair logit
            }
        }
    }

#pragma unroll
    for (int i = 0; i < 8; ++i) {
        rs[i] += __shfl_xor_sync(0xffffffffu, rs[i], 1);
        rs[i] += __shfl_xor_sync(0xffffffffu, rs[i], 2);
    }
    if (qc == 0) {
#pragma unroll
        for (int i = 0; i < 8; ++i)
            atomicAdd(&rowS[wm * 64 + (i >> 1) * 16 + qr + (i & 1) * 8], rs[i]);
    }
#pragma unroll
    for (int i = 0; i < 16; ++i) {
        cs[i] += __shfl_xor_sync(0xffffffffu, cs[i], 4);
        cs[i] += __shfl_xor_sync(0xffffffffu, cs[i], 8);
        cs[i] += __shfl_xor_sync(0xffffffffu, cs[i], 16);
    }
    if (lane < 4) {
#pragma unroll
        for (int i = 0; i < 16; ++i)
            atomicAdd(&colS[wn * 64 + (i >> 1) * 8 + 2 * lane + (i & 1)], cs[i]);
    }
    if (has_pos) {
#pragma unroll
        for (int m = 16; m; m >>= 1) pos += __shfl_xor_sync(0xffffffffu, pos, m);
        if (lane == 0) atomicAdd(posS, pos);
    }
    __syncthreads();

    atomicAdd(&g_S[rowbase + tid], rowS[tid]);
    if (!diag) atomicAdd(&g_S[colbase + tid], colS[tid]);
    if (has_pos && tid == 0) atomicAdd(&g_acc[6], posS[0] * 2.0f);
}

// ---------------- finalize (parallel, single launch, self-resetting) ----------
__global__ void final_kernel(const int* __restrict__ target,
                             const float* __restrict__ w_onnpu,
                             float* __restrict__ out) {
    __shared__ float wsf[4];
    __shared__ int   wsi[4];
    __shared__ int   lastflag;
    int tid  = threadIdx.x;
    int lane = tid & 31, wid = tid >> 5;
    int i = blockIdx.x * 128 + tid;         // 0..8191

    float l = __logf(g_S[i]);
    int np = (i < BATCH) ? (target[i] == 1) : 0;
#pragma unroll
    for (int m = 16; m; m >>= 1) {
        l  += __shfl_xor_sync(0xffffffffu, l, m);
        np += __shfl_xor_sync(0xffffffffu, np, m);
    }
    if (lane == 0) { wsf[wid] = l; wsi[wid] = np; }
    __syncthreads();
    if (tid == 0) {
        float bs = wsf[0] + wsf[1] + wsf[2] + wsf[3];
        int   bn = wsi[0] + wsi[1] + wsi[2] + wsi[3];
        atomicAdd(&g_acc[7], bs);
        if (bn) atomicAdd(&g_np, bn);
        __threadfence();
        unsigned old = atomicInc(&g_ctr, 63u);   // wraps to 0 on last arrival
        lastflag = (old == 63u);
    }
    __syncthreads();
    if (lastflag) {
        if (tid == 0) {
            float logsum = g_acc[7];
            float n_pos = fmaxf(1.0f, (float)g_np);
            float n_unl = fmaxf(1.0f, (float)(BATCH - g_np));
            float nt = (logsum - g_acc[6]) / (float)NROWS;
            float li, lj;
            {
                float prisk = PRIOR_PRIME / n_pos * g_acc[0];
                float nrisk = (1.0f - PRIOR_PRIME) / (n_unl * (1.0f - PRIOR)) * g_acc[2]
                            - (1.0f - PRIOR_PRIME) * PRIOR / (n_pos * (1.0f - PRIOR)) * g_acc[1];
                li = (nrisk < 0.0f) ? -nrisk : (prisk + nrisk);
            }
            {
                float prisk = PRIOR_PRIME / n_pos * g_acc[3];
                float nrisk = (1.0f - PRIOR_PRIME) / (n_unl * (1.0f - PRIOR)) * g_acc[5]
                            - (1.0f - PRIOR_PRIME) * PRIOR / (n_pos * (1.0f - PRIOR)) * g_acc[4];
                lj = (nrisk < 0.0f) ? -nrisk : (prisk + nrisk);
            }
            float w = w_onnpu[0];
            out[0] = w * 0.5f * (li + lj) + (1.0f - w) * nt;
#pragma unroll
            for (int k = 0; k < 8; ++k) g_acc[k] = 0.0f;
            g_np = 0;
        }
        for (int k = tid; k < NROWS; k += 128) g_S[k] = 0.0f;
    }
}

// ---------------- launch ------------------------------------------------------
extern "C" void kernel_launch(void* const* d_in, const int* in_sizes, int n_in,
                              void* d_out, int out_size) {
    const float* h_i = (const float*)d_in[0];
    const float* h_j = (const float*)d_in[1];
    const float* z_i = (const float*)d_in[2];
    const float* z_j = (const float*)d_in[3];
    const int*   tgt = (const int*)  d_in[4];
    const float* W   = (const float*)d_in[5];
    const float* b   = (const float*)d_in[6];
    const float* wgt = (const float*)d_in[7];
    float* out = (float*)d_out;

    static int smem_set = 0;
    const int SIM_SMEM = 65536 + (128 + 128 + 1) * (int)sizeof(float);  // 66564
    if (!smem_set) {
        cudaFuncSetAttribute(sim_kernel,
                             cudaFuncAttributeMaxDynamicSharedMemorySize, SIM_SMEM);
        cudaFuncSetAttribute(prep_kernel,
                             cudaFuncAttributeMaxDynamicSharedMemorySize, PREP_SMEM);
        smem_set = 1;
    }

    prep_kernel<<<PU_BLOCKS + 1024, 256, PREP_SMEM>>>(h_i, h_j, z_i, z_j, W, b, tgt);
    sim_kernel<<<NPAIRS, 128, SIM_SMEM>>>();
    final_kernel<<<64, 128>>>(tgt, wgt, out);
}